// round 14
// baseline (speedup 1.0000x reference)
#include <cuda_runtime.h>
#include <cuda_fp16.h>
#include <math.h>
#include <stdint.h>

#define NB   2
#define IH   128
#define IW   128
#define IC   192
#define LTOT 4096
#define MQ   4225   // 65*65
#define MQP  4352   // 34*128
#define NOUT 768
#define KD   192

// ---------------- scratch ----------------
__device__ __half g_fdh[NB][LTOT][KD], g_fdl[NB][LTOT][KD];
__device__ __half g_bdh[NB][LTOT][KD], g_bdl[NB][LTOT][KD];
__device__ float g_n2[NB][LTOT];
__device__ float g_norm[NB][LTOT];
__device__ float g_mmT[LTOT];                       // mask, transposed index
__device__ float g_D[NB][(size_t)LTOT * LTOT];      // D
__device__ float g_S[NB][(size_t)LTOT * LTOT];      // F1
__device__ __half g_AT2[NB][(size_t)LTOT * LTOT];   // attention (transposed), fp16
__device__ __half g_Ath[NB][(size_t)MQP * MQP];     // A-tilde (fp16)
__device__ __half g_Bth[NB][(size_t)NOUT * MQP];    // B (fp16)

__device__ __forceinline__ void split_h(float v, __half& h, __half& l) {
    h = __float2half_rn(v);
    l = __float2half_rn(v - __half2float(h));
}
__device__ __forceinline__ uint32_t smem_u32(const void* p) {
    uint32_t a;
    asm("{ .reg .u64 t; cvta.to.shared.u64 t, %1; cvt.u32.u64 %0, t; }" : "=r"(a) : "l"(p));
    return a;
}

#define MMA(ac, a, bb) \
    asm volatile("mma.sync.aligned.m16n8k16.row.col.f32.f16.f16.f32 " \
        "{%0,%1,%2,%3}, {%4,%5,%6,%7}, {%8,%9}, {%0,%1,%2,%3};" \
        : "+f"((ac)[0]), "+f"((ac)[1]), "+f"((ac)[2]), "+f"((ac)[3]) \
        : "r"((a)[0]), "r"((a)[1]), "r"((a)[2]), "r"((a)[3]), \
          "r"((bb)[0]), "r"((bb)[1]))

#define LDSM4(r0, r1, r2, r3, addr) \
    asm volatile("ldmatrix.sync.aligned.m8n8.x4.shared.b16 {%0,%1,%2,%3}, [%4];" \
        : "=r"(r0), "=r"(r1), "=r"(r2), "=r"(r3) : "r"(addr))

// ---------------- K1: downsample + pack fp16 hi/lo + |bd|^2 ---------------
__global__ void k_pack(const float* __restrict__ f, const float* __restrict__ b) {
    int i = blockIdx.z, p = blockIdx.x;
    int x = p >> 6, y = p & 63;
    size_t base = (((size_t)i * IH + 2 * x) * IW + 2 * y) * IC;
    int c = threadIdx.x;
    float fv = f[base + c], bv = b[base + c];
    __half h, l;
    split_h(fv, h, l); g_fdh[i][p][c] = h; g_fdl[i][p][c] = l;
    split_h(bv, h, l); g_bdh[i][p][c] = h; g_bdl[i][p][c] = l;

    __shared__ float sh[192];
    sh[c] = bv * bv;
    __syncthreads();
    if (c < 64) sh[c] += sh[c + 64] + sh[c + 128];
    __syncthreads();
    if (c < 32) {
        float v = sh[c] + sh[c + 32];
        #pragma unroll
        for (int o = 16; o > 0; o >>= 1) v += __shfl_down_sync(0xffffffffu, v, o);
        if (c == 0) g_n2[i][p] = v;
    }
}

// ---------------- K1b: patch norms + transposed mask ------------------------
__global__ void k_norm_mm(const float* __restrict__ mask) {
    int i = blockIdx.z;
    int l = blockIdx.x * 128 + threadIdx.x;
    int u = l >> 6, v = l & 63;
    float s = 0.f;
    #pragma unroll
    for (int a = -1; a <= 1; ++a)
        #pragma unroll
        for (int bo = -1; bo <= 1; ++bo) {
            int uu = u + a, vv = v + bo;
            if ((unsigned)uu < 64u && (unsigned)vv < 64u) s += g_n2[i][uu * 64 + vv];
        }
    g_norm[i][l] = fmaxf(sqrtf(s), 1e-4f);
    if (i == 0) {
        float ms = 0.f;
        #pragma unroll
        for (int a = -1; a <= 1; ++a)
            #pragma unroll
            for (int bo = -1; bo <= 1; ++bo) {
                int uu = u + a, vv = v + bo;
                if ((unsigned)uu < 64u && (unsigned)vv < 64u) ms += mask[(2 * uu) * IW + 2 * vv];
            }
        g_mmT[((l & 63) << 6) | (l >> 6)] = (ms == 0.0f) ? 1.0f : 0.0f;
    }
}

// ---- shared-tile copy helper ------------------------------------------------
#define TSTR 40
#define TILEB (128 * TSTR)

__device__ __forceinline__ void cp_tile(const __half* __restrict__ src,
                                        int ld, int row0, int k0,
                                        __half* dst, int tid) {
    #pragma unroll
    for (int j = 0; j < 2; ++j) {
        int idx = j * 256 + tid;
        int r = idx >> 2, cc = idx & 3;
        uint32_t d = smem_u32(dst + r * TSTR + cc * 8);
        const void* s = src + (size_t)(row0 + r) * ld + k0 + cc * 8;
        asm volatile("cp.async.ca.shared.global [%0], [%1], 16;" :: "r"(d), "l"(s));
    }
}

// ---- K2: gemm_D: D = fd*bd^T, fp16 3-pass, 2-stage, 2 CTAs/SM --------------
__global__ __launch_bounds__(256, 2) void k_gemm_D() {
    constexpr int KIT = 6;
    extern __shared__ __half smg[];
    int i = blockIdx.z, tid = threadIdx.x;
    int wid = tid >> 5, lane = tid & 31;
    int wm = wid & 1, wn = wid >> 1;
    int g = lane >> 2, t = lane & 3;
    int bm = blockIdx.y << 7, bn = blockIdx.x << 7;
    const __half* Ah = &g_fdh[i][0][0];
    const __half* Al = &g_fdl[i][0][0];
    const __half* Bh = &g_bdh[i][0][0];
    const __half* Bl = &g_bdl[i][0][0];
    float acc[4][4][4] = {};

    int a_row  = wm * 64 + (lane & 15);
    int a_koff = (lane >> 4) << 3;
    int b_row  = wn * 32 + (lane & 7) + ((lane >> 4) << 3);
    int b_koff = ((lane >> 3) & 1) << 3;

    {
        cp_tile(Ah, KD, bm, 0, smg, tid);
        cp_tile(Al, KD, bm, 0, smg + TILEB, tid);
        cp_tile(Bh, KD, bn, 0, smg + 2 * TILEB, tid);
        cp_tile(Bl, KD, bn, 0, smg + 3 * TILEB, tid);
        asm volatile("cp.async.commit_group;" ::: "memory");
    }
    for (int it = 0; it < KIT; ++it) {
        int st = it & 1;
        if (it + 1 < KIT) {
            __half* b0 = smg + (st ^ 1) * 4 * TILEB;
            int k0 = (it + 1) << 5;
            cp_tile(Ah, KD, bm, k0, b0, tid);
            cp_tile(Al, KD, bm, k0, b0 + TILEB, tid);
            cp_tile(Bh, KD, bn, k0, b0 + 2 * TILEB, tid);
            cp_tile(Bl, KD, bn, k0, b0 + 3 * TILEB, tid);
            asm volatile("cp.async.commit_group;" ::: "memory");
            asm volatile("cp.async.wait_group 1;" ::: "memory");
        } else {
            asm volatile("cp.async.wait_group 0;" ::: "memory");
        }
        __syncthreads();
        uint32_t sA_h = smem_u32(smg + st * 4 * TILEB);
        uint32_t sA_l = sA_h + TILEB * 2;
        uint32_t sB_h = sA_h + 4 * TILEB;
        uint32_t sB_l = sA_h + 6 * TILEB;
        #pragma unroll
        for (int ks = 0; ks < 2; ++ks) {
            uint32_t bh[4][2], bl[4][2];
            #pragma unroll
            for (int pr = 0; pr < 2; ++pr) {
                uint32_t off = 2u * ((b_row + pr * 16) * TSTR + ks * 16 + b_koff);
                LDSM4(bh[2*pr][0], bh[2*pr][1], bh[2*pr+1][0], bh[2*pr+1][1], sB_h + off);
                LDSM4(bl[2*pr][0], bl[2*pr][1], bl[2*pr+1][0], bl[2*pr+1][1], sB_l + off);
            }
            #pragma unroll
            for (int mi = 0; mi < 4; ++mi) {
                uint32_t ah[4], al[4];
                uint32_t off = 2u * ((a_row + mi * 16) * TSTR + ks * 16 + a_koff);
                LDSM4(ah[0], ah[1], ah[2], ah[3], sA_h + off);
                LDSM4(al[0], al[1], al[2], al[3], sA_l + off);
                #pragma unroll
                for (int ni = 0; ni < 4; ++ni) {
                    MMA(acc[mi][ni], ah, bh[ni]);
                    MMA(acc[mi][ni], ah, bl[ni]);
                    MMA(acc[mi][ni], al, bh[ni]);
                }
            }
        }
        __syncthreads();
    }
    float* Cm = g_D[i];
    #pragma unroll
    for (int mi = 0; mi < 4; ++mi)
        #pragma unroll
        for (int ni = 0; ni < 4; ++ni) {
            int row = bm + wm * 64 + mi * 16 + g;
            int col = bn + wn * 32 + ni * 8 + 2 * t;
            *(float2*)(Cm + (size_t)row * 4096 + col)       = make_float2(acc[mi][ni][0], acc[mi][ni][1]);
            *(float2*)(Cm + (size_t)(row + 8) * 4096 + col) = make_float2(acc[mi][ni][2], acc[mi][ni][3]);
        }
}

// ---- K9: gemm_out: single-pass A(fp16) x B(fp16), 3-stage, 3 CTAs/SM -------
#define OSTAGE (2 * TILEB)   // halves per stage (A, B)
__global__ __launch_bounds__(256, 3) void k_gemm_out(float* __restrict__ outp) {
    constexpr int KIT = 133;
    extern __shared__ __half smg[];   // 3 stages * OSTAGE
    int i = blockIdx.z, tid = threadIdx.x;
    int wid = tid >> 5, lane = tid & 31;
    int wm = wid & 1, wn = wid >> 1;
    int g = lane >> 2, t = lane & 3;
    int bm = blockIdx.y << 7, bn = blockIdx.x << 7;
    const __half* A  = g_Ath[i];
    const __half* Bh = g_Bth[i];
    float acc[4][4][4] = {};

    int a_row  = wm * 64 + (lane & 15);
    int a_koff = (lane >> 4) << 3;
    int b_row  = wn * 32 + (lane & 7) + ((lane >> 4) << 3);
    int b_koff = ((lane >> 3) & 1) << 3;

    #pragma unroll
    for (int s = 0; s < 2; ++s) {
        __half* b0 = smg + s * OSTAGE;
        int k0 = s << 5;
        cp_tile(A,  MQP, bm, k0, b0, tid);
        cp_tile(Bh, MQP, bn, k0, b0 + TILEB, tid);
        asm volatile("cp.async.commit_group;" ::: "memory");
    }
    for (int it = 0; it < KIT; ++it) {
        if (it + 1 < KIT) asm volatile("cp.async.wait_group 1;" ::: "memory");
        else              asm volatile("cp.async.wait_group 0;" ::: "memory");
        __syncthreads();
        int st = it % 3;
        uint32_t sA   = smem_u32(smg + st * OSTAGE);
        uint32_t sB_h = sA + 2 * TILEB;
        #pragma unroll
        for (int ks = 0; ks < 2; ++ks) {
            uint32_t bh[4][2];
            #pragma unroll
            for (int pr = 0; pr < 2; ++pr) {
                uint32_t off = 2u * ((b_row + pr * 16) * TSTR + ks * 16 + b_koff);
                LDSM4(bh[2*pr][0], bh[2*pr][1], bh[2*pr+1][0], bh[2*pr+1][1], sB_h + off);
            }
            #pragma unroll
            for (int mi = 0; mi < 4; ++mi) {
                uint32_t ah[4];
                uint32_t off = 2u * ((a_row + mi * 16) * TSTR + ks * 16 + a_koff);
                LDSM4(ah[0], ah[1], ah[2], ah[3], sA + off);
                #pragma unroll
                for (int ni = 0; ni < 4; ++ni)
                    MMA(acc[mi][ni], ah, bh[ni]);
            }
        }
        if (it + 2 < KIT) {
            __half* b0 = smg + ((it + 2) % 3) * OSTAGE;
            int k0 = (it + 2) << 5;
            cp_tile(A,  MQP, bm, k0, b0, tid);
            cp_tile(Bh, MQP, bn, k0, b0 + TILEB, tid);
            asm volatile("cp.async.commit_group;" ::: "memory");
        }
    }
    // fused parity-scatter epilogue
    #pragma unroll
    for (int mi = 0; mi < 4; ++mi)
        #pragma unroll
        for (int ni = 0; ni < 4; ++ni) {
            int row0 = bm + wm * 64 + mi * 16 + g;
            int col = bn + wn * 32 + ni * 8 + 2 * t;
            int par = col / IC, c = col - par * IC;
            int rx = par >> 1, ry = par & 1;
            #pragma unroll
            for (int h2 = 0; h2 < 2; ++h2) {
                int row = row0 + 8 * h2;
                if (row < MQ) {
                    int y0 = row / 65, x0 = row - y0 * 65;
                    int X = 2 * x0 + rx - 1, Y = 2 * y0 + ry - 1;
                    if ((unsigned)X < 128u && (unsigned)Y < 128u) {
                        float2 v = make_float2(0.25f * acc[mi][ni][2 * h2],
                                               0.25f * acc[mi][ni][2 * h2 + 1]);
                        *(float2*)(outp + (((size_t)i * IH + X) * IW + Y) * IC + c) = v;
                    }
                }
            }
        }
}

// ---- K3: fused score + fuse1, 2 column chunks, 2 CTAs/SM -------------------
// Block: 4 F1 rows (p0..p0+3) x 2048 cols (c0..c0+2047). Band halo 68.
#define BW  2184   // band width (floats), 546 float4
#define SWW 2056   // S temp row stride (holds cols c0-1 .. c0+2048 at j=0..2049)
__global__ __launch_bounds__(512, 2) void k_scoref() {
    extern __shared__ float sb[];   // 8*BW floats; reused for S (6*SWW)
    int i = blockIdx.z;
    int p0 = blockIdx.x << 2;
    int c0 = blockIdx.y << 11;
    int tid = threadIdx.x;
    const float* D = g_D[i];
    float acc_s[6][4] = {};
    float acc_e[6] = {};
    int ce = (tid == 0) ? -1 : 2048;   // extra cols (threads 0,1)

    #pragma unroll
    for (int a = -1; a <= 1; ++a) {
        __syncthreads();
        int rbase = p0 - 2 + a * 64;
        int gbase = c0 + a * 64 - 68;
        for (int idx = tid; idx < 8 * (BW / 4); idx += 512) {
            int s = idx / (BW / 4), c4 = idx - s * (BW / 4);
            int row = rbase + s;
            int g = gbase + c4 * 4;
            float4 v = make_float4(0.f, 0.f, 0.f, 0.f);
            if ((unsigned)row < 4096u) {
                const float* rp = D + (size_t)row * 4096;
                if (g >= 0 && g + 3 < 4096) v = *(const float4*)(rp + g);
                else {
                    if ((unsigned)(g + 0) < 4096u) v.x = rp[g];
                    if ((unsigned)(g + 1) < 4096u) v.y = rp[g + 1];
                    if ((unsigned)(g + 2) < 4096u) v.z = rp[g + 2];
                    if ((unsigned)(g + 3) < 4096u) v.w = rp[g + 3];
                }
            }
            *(float4*)(sb + s * BW + c4 * 4) = v;
        }
        __syncthreads();
        #pragma unroll
        for (int r = 0; r < 6; ++r) {
            int pr = p0 - 1 + r;
            if ((unsigned)pr >= 4096u) continue;
            int xr = pr >> 6, yr = pr & 63;
            if ((unsigned)(xr + a) >= 64u) continue;
            #pragma unroll
            for (int k = 0; k < 4; ++k) {
                int cl = tid + (k << 9);
                int l = c0 + cl;
                int u = l >> 6, v = l & 63;
                if ((unsigned)(u + a) >= 64u) continue;
                #pragma unroll
                for (int b = -1; b <= 1; ++b) {
                    if ((unsigned)(v + b) < 64u && (unsigned)(yr + b) < 64u)
                        acc_s[r][k] += sb[(r + b + 1) * BW + cl + b + 68];
                }
            }
            if (tid < 2) {
                int l = c0 + ce;
                if ((unsigned)l < 4096u) {
                    int u = l >> 6, v = l & 63;
                    if ((unsigned)(u + a) < 64u) {
                        #pragma unroll
                        for (int b = -1; b <= 1; ++b) {
                            if ((unsigned)(v + b) < 64u && (unsigned)(yr + b) < 64u)
                                acc_e[r] += sb[(r + b + 1) * BW + ce + b + 68];
                        }
                    }
                }
            }
        }
    }
    __syncthreads();
    const float* nm = g_norm[i];
    #pragma unroll
    for (int k = 0; k < 4; ++k) {
        int cl = tid + (k << 9);
        float inv = 1.0f / nm[c0 + cl];
        #pragma unroll
        for (int r = 0; r < 6; ++r)
            sb[r * SWW + cl + 1] = acc_s[r][k] * inv;
    }
    if (tid < 2) {
        int l = c0 + ce;
        float inv = ((unsigned)l < 4096u) ? (1.0f / nm[l]) : 0.f;
        int j = (tid == 0) ? 0 : 2049;
        #pragma unroll
        for (int r = 0; r < 6; ++r)
            sb[r * SWW + j] = acc_e[r] * inv;
    }
    __syncthreads();
    float* F1 = g_S[i] + (size_t)p0 * 4096 + c0;
    #pragma unroll
    for (int k = 0; k < 4; ++k) {
        int qc = tid + (k << 9);
        #pragma unroll
        for (int qi = 0; qi < 4; ++qi) {
            float s = 0.f;
            #pragma unroll
            for (int d = -1; d <= 1; ++d)
                s += sb[(qi + 1 + d) * SWW + qc + d + 1];
            F1[(size_t)qi * 4096 + qc] = s;
        }
    }
}

// -- K5: fused fuse2 + softmax, 2 rows/block; reads F1 (g_S), writes AT2 fp16
__global__ __launch_bounds__(256) void k_fuse2sm() {
    extern __shared__ float smf[];     // 4 * 4160 floats
    __shared__ float red[256];
    int i = blockIdx.z, pt0 = blockIdx.x << 1, tid = threadIdx.x;
    const float* F1 = g_S[i];

    #pragma unroll
    for (int d = 0; d < 4; ++d) {
        int pz = pt0 + d - 1;
        float* dst = smf + d * 4160;
        if ((unsigned)pz < 4096u) {
            int rd = ((pz & 63) << 6) | (pz >> 6);
            const float* row = F1 + (size_t)rd * 4096;
            #pragma unroll
            for (int j = 0; j < 16; ++j) {
                int c = tid + j * 256;
                dst[(c & 63) * 65 + (c >> 6)] = row[c];
            }
        } else {
            #pragma unroll
            for (int j = 0; j < 16; ++j) {
                int c = tid + j * 256;
                dst[(c & 63) * 65 + (c >> 6)] = 0.f;
            }
        }
    }
    __syncthreads();

    #pragma unroll
    for (int qi = 0; qi < 2; ++qi) {
        float vals[16], msk[16];
        float mx = -3.4e38f;
        #pragma unroll
        for (int j = 0; j < 16; ++j) {
            int qt = tid + j * 256;
            float s = 0.f;
            #pragma unroll
            for (int d = 0; d < 3; ++d) {
                int z = qt + d - 1;
                if ((unsigned)z < 4096u)
                    s += smf[(qi + d) * 4160 + (z >> 6) * 65 + (z & 63)];
            }
            float m = g_mmT[qt];
            msk[j] = m;
            float v = s * m * 10.0f;
            vals[j] = v;
            mx = fmaxf(mx, v);
        }
        red[tid] = mx; __syncthreads();
        #pragma unroll
        for (int s = 128; s > 0; s >>= 1) { if (tid < s) red[tid] = fmaxf(red[tid], red[tid + s]); __syncthreads(); }
        mx = red[0]; __syncthreads();
        float sum = 0.f;
        #pragma unroll
        for (int j = 0; j < 16; ++j) { vals[j] = expf(vals[j] - mx); sum += vals[j]; }
        red[tid] = sum; __syncthreads();
        #pragma unroll
        for (int s = 128; s > 0; s >>= 1) { if (tid < s) red[tid] += red[tid + s]; __syncthreads(); }
        float inv = 1.0f / red[0];
        __half* out = g_AT2[i] + (size_t)(pt0 + qi) * 4096;
        #pragma unroll
        for (int j = 0; j < 16; ++j) {
            int qt = tid + j * 256;
            out[qt] = __float2half_rn(vals[j] * inv * msk[j]);
        }
        __syncthreads();
    }
}

// ------ K7: build A-tilde (primed ordering, reads AT2 fp16, fp16 out) -------
__global__ void k_Abuild() {
    int i = blockIdx.z;
    int q0p = blockIdx.y;
    int lpp = blockIdx.x * 256 + threadIdx.x;
    int y0 = q0p / 65, x0 = q0p % 65;
    int vp = lpp / 65, up = lpp % 65;
    const __half* AT = g_AT2[i];
    float s = 0.f;
    #pragma unroll
    for (int a = 0; a < 2; ++a) {
        int xr = x0 - a, ur = up - a;
        if ((unsigned)xr < 64u && (unsigned)ur < 64u) {
            #pragma unroll
            for (int bo = 0; bo < 2; ++bo) {
                int yr = y0 - bo, vr = vp - bo;
                if ((unsigned)yr < 64u && (unsigned)vr < 64u)
                    s += __half2float(AT[(size_t)(yr * 64 + xr) * 4096 + (vr * 64 + ur)]);
            }
        }
    }
    g_Ath[i][(size_t)q0p * MQP + lpp] = __float2half_rn(s);
}

// ------ K8: build Bt[n][lp'] (fp16, primed K ordering) ----------------------
__global__ void k_Btbuild(const float* __restrict__ b) {
    int i = blockIdx.z;
    int n = blockIdx.y;
    int lpp = blockIdx.x * 256 + threadIdx.x;
    int par = n / IC, c = n - par * IC;
    int rx = par >> 1, ry = par & 1;
    int vp = lpp / 65, up = lpp % 65;
    int X = 2 * up + rx - 1, Y = 2 * vp + ry - 1;
    float val = 0.f;
    if (lpp < MQ && (unsigned)X < 128u && (unsigned)Y < 128u)
        val = b[(((size_t)i * IH + X) * IW + Y) * IC + c];
    g_Bth[i][(size_t)n * MQP + lpp] = __float2half_rn(val);
}

// ---------------- launch -----------------------------------------------------
extern "C" void kernel_launch(void* const* d_in, const int* in_sizes, int n_in,
                              void* d_out, int out_size) {
    const float* f    = (const float*)d_in[0];
    const float* b    = (const float*)d_in[1];
    const float* mask = (const float*)d_in[2];
    float* out = (float*)d_out;

    const int gemmD_smem = 8 * TILEB * 2;       // 81920 B
    const int gemmO_smem = 2 * OSTAGE * 3;      // 61440 B
    const int sf_smem    = 8 * BW * 4;          // 69888 B
    const int f2_smem    = 4 * 4160 * 4;        // 66560 B
    cudaFuncSetAttribute(k_gemm_D,   cudaFuncAttributeMaxDynamicSharedMemorySize, gemmD_smem);
    cudaFuncSetAttribute(k_gemm_out, cudaFuncAttributeMaxDynamicSharedMemorySize, gemmO_smem);
    cudaFuncSetAttribute(k_scoref,   cudaFuncAttributeMaxDynamicSharedMemorySize, sf_smem);
    cudaFuncSetAttribute(k_fuse2sm,  cudaFuncAttributeMaxDynamicSharedMemorySize, f2_smem);

    k_pack    <<<dim3(4096, 1, NB), 192>>>(f, b);
    k_norm_mm <<<dim3(32,   1, NB), 128>>>(mask);
    k_gemm_D  <<<dim3(32, 32, NB), 256, gemmD_smem>>>();
    k_scoref  <<<dim3(1024, 2, NB), 512, sf_smem>>>();
    k_fuse2sm <<<dim3(2048, 1, NB), 256, f2_smem>>>();
    k_Abuild  <<<dim3(17, MQ, NB), 256>>>();
    k_Btbuild <<<dim3(17, NOUT, NB), 256>>>(b);
    k_gemm_out<<<dim3(6, 34, NB), 256, gemmO_smem>>>(out);
}

// round 15
// speedup vs baseline: 1.0303x; 1.0303x over previous
#include <cuda_runtime.h>
#include <cuda_fp16.h>
#include <math.h>
#include <stdint.h>

#define NB   2
#define IH   128
#define IW   128
#define IC   192
#define LTOT 4096
#define MQ   4225   // 65*65
#define MQP  4352   // 34*128
#define NOUT 768
#define KD   192

// ---------------- scratch ----------------
__device__ __half g_fdh[NB][LTOT][KD], g_fdl[NB][LTOT][KD];
__device__ __half g_bdh[NB][LTOT][KD], g_bdl[NB][LTOT][KD];
__device__ float g_n2[NB][LTOT];
__device__ float g_norm[NB][LTOT];
__device__ float g_mmT[LTOT];                       // mask, transposed index
__device__ float g_D[NB][(size_t)LTOT * LTOT];      // D
__device__ float g_S[NB][(size_t)LTOT * LTOT];      // F1
__device__ __half g_AT2[NB][(size_t)LTOT * LTOT];   // attention (transposed), fp16
__device__ __half g_Ath[NB][(size_t)MQP * MQP];     // A-tilde (fp16)
__device__ __half g_Bth[NB][(size_t)NOUT * MQP];    // B (fp16)

__device__ __forceinline__ void split_h(float v, __half& h, __half& l) {
    h = __float2half_rn(v);
    l = __float2half_rn(v - __half2float(h));
}
__device__ __forceinline__ uint32_t smem_u32(const void* p) {
    uint32_t a;
    asm("{ .reg .u64 t; cvta.to.shared.u64 t, %1; cvt.u32.u64 %0, t; }" : "=r"(a) : "l"(p));
    return a;
}

#define MMA(ac, a, bb) \
    asm volatile("mma.sync.aligned.m16n8k16.row.col.f32.f16.f16.f32 " \
        "{%0,%1,%2,%3}, {%4,%5,%6,%7}, {%8,%9}, {%0,%1,%2,%3};" \
        : "+f"((ac)[0]), "+f"((ac)[1]), "+f"((ac)[2]), "+f"((ac)[3]) \
        : "r"((a)[0]), "r"((a)[1]), "r"((a)[2]), "r"((a)[3]), \
          "r"((bb)[0]), "r"((bb)[1]))

#define LDSM4(r0, r1, r2, r3, addr) \
    asm volatile("ldmatrix.sync.aligned.m8n8.x4.shared.b16 {%0,%1,%2,%3}, [%4];" \
        : "=r"(r0), "=r"(r1), "=r"(r2), "=r"(r3) : "r"(addr))

// ---------------- K1: downsample + pack fp16 hi/lo + |bd|^2 ---------------
__global__ void k_pack(const float* __restrict__ f, const float* __restrict__ b) {
    int i = blockIdx.z, p = blockIdx.x;
    int x = p >> 6, y = p & 63;
    size_t base = (((size_t)i * IH + 2 * x) * IW + 2 * y) * IC;
    int c = threadIdx.x;
    float fv = f[base + c], bv = b[base + c];
    __half h, l;
    split_h(fv, h, l); g_fdh[i][p][c] = h; g_fdl[i][p][c] = l;
    split_h(bv, h, l); g_bdh[i][p][c] = h; g_bdl[i][p][c] = l;

    __shared__ float sh[192];
    sh[c] = bv * bv;
    __syncthreads();
    if (c < 64) sh[c] += sh[c + 64] + sh[c + 128];
    __syncthreads();
    if (c < 32) {
        float v = sh[c] + sh[c + 32];
        #pragma unroll
        for (int o = 16; o > 0; o >>= 1) v += __shfl_down_sync(0xffffffffu, v, o);
        if (c == 0) g_n2[i][p] = v;
    }
}

// ---------------- K1b: patch norms + transposed mask ------------------------
__global__ void k_norm_mm(const float* __restrict__ mask) {
    int i = blockIdx.z;
    int l = blockIdx.x * 128 + threadIdx.x;
    int u = l >> 6, v = l & 63;
    float s = 0.f;
    #pragma unroll
    for (int a = -1; a <= 1; ++a)
        #pragma unroll
        for (int bo = -1; bo <= 1; ++bo) {
            int uu = u + a, vv = v + bo;
            if ((unsigned)uu < 64u && (unsigned)vv < 64u) s += g_n2[i][uu * 64 + vv];
        }
    g_norm[i][l] = fmaxf(sqrtf(s), 1e-4f);
    if (i == 0) {
        float ms = 0.f;
        #pragma unroll
        for (int a = -1; a <= 1; ++a)
            #pragma unroll
            for (int bo = -1; bo <= 1; ++bo) {
                int uu = u + a, vv = v + bo;
                if ((unsigned)uu < 64u && (unsigned)vv < 64u) ms += mask[(2 * uu) * IW + 2 * vv];
            }
        g_mmT[((l & 63) << 6) | (l >> 6)] = (ms == 0.0f) ? 1.0f : 0.0f;
    }
}

// ---- shared-tile copy helper ------------------------------------------------
#define TSTR 40
#define TILEB (128 * TSTR)

__device__ __forceinline__ void cp_tile(const __half* __restrict__ src,
                                        int ld, int row0, int k0,
                                        __half* dst, int tid) {
    #pragma unroll
    for (int j = 0; j < 2; ++j) {
        int idx = j * 256 + tid;
        int r = idx >> 2, cc = idx & 3;
        uint32_t d = smem_u32(dst + r * TSTR + cc * 8);
        const void* s = src + (size_t)(row0 + r) * ld + k0 + cc * 8;
        asm volatile("cp.async.ca.shared.global [%0], [%1], 16;" :: "r"(d), "l"(s));
    }
}

// ---- K2: gemm_D: D = fd*bd^T, fp16 3-pass, 2-stage, 2 CTAs/SM --------------
__global__ __launch_bounds__(256, 2) void k_gemm_D() {
    constexpr int KIT = 6;
    extern __shared__ __half smg[];
    int i = blockIdx.z, tid = threadIdx.x;
    int wid = tid >> 5, lane = tid & 31;
    int wm = wid & 1, wn = wid >> 1;
    int g = lane >> 2, t = lane & 3;
    int bm = blockIdx.y << 7, bn = blockIdx.x << 7;
    const __half* Ah = &g_fdh[i][0][0];
    const __half* Al = &g_fdl[i][0][0];
    const __half* Bh = &g_bdh[i][0][0];
    const __half* Bl = &g_bdl[i][0][0];
    float acc[4][4][4] = {};

    int a_row  = wm * 64 + (lane & 15);
    int a_koff = (lane >> 4) << 3;
    int b_row  = wn * 32 + (lane & 7) + ((lane >> 4) << 3);
    int b_koff = ((lane >> 3) & 1) << 3;

    {
        cp_tile(Ah, KD, bm, 0, smg, tid);
        cp_tile(Al, KD, bm, 0, smg + TILEB, tid);
        cp_tile(Bh, KD, bn, 0, smg + 2 * TILEB, tid);
        cp_tile(Bl, KD, bn, 0, smg + 3 * TILEB, tid);
        asm volatile("cp.async.commit_group;" ::: "memory");
    }
    for (int it = 0; it < KIT; ++it) {
        int st = it & 1;
        if (it + 1 < KIT) {
            __half* b0 = smg + (st ^ 1) * 4 * TILEB;
            int k0 = (it + 1) << 5;
            cp_tile(Ah, KD, bm, k0, b0, tid);
            cp_tile(Al, KD, bm, k0, b0 + TILEB, tid);
            cp_tile(Bh, KD, bn, k0, b0 + 2 * TILEB, tid);
            cp_tile(Bl, KD, bn, k0, b0 + 3 * TILEB, tid);
            asm volatile("cp.async.commit_group;" ::: "memory");
            asm volatile("cp.async.wait_group 1;" ::: "memory");
        } else {
            asm volatile("cp.async.wait_group 0;" ::: "memory");
        }
        __syncthreads();
        uint32_t sA_h = smem_u32(smg + st * 4 * TILEB);
        uint32_t sA_l = sA_h + TILEB * 2;
        uint32_t sB_h = sA_h + 4 * TILEB;
        uint32_t sB_l = sA_h + 6 * TILEB;
        #pragma unroll
        for (int ks = 0; ks < 2; ++ks) {
            uint32_t bh[4][2], bl[4][2];
            #pragma unroll
            for (int pr = 0; pr < 2; ++pr) {
                uint32_t off = 2u * ((b_row + pr * 16) * TSTR + ks * 16 + b_koff);
                LDSM4(bh[2*pr][0], bh[2*pr][1], bh[2*pr+1][0], bh[2*pr+1][1], sB_h + off);
                LDSM4(bl[2*pr][0], bl[2*pr][1], bl[2*pr+1][0], bl[2*pr+1][1], sB_l + off);
            }
            #pragma unroll
            for (int mi = 0; mi < 4; ++mi) {
                uint32_t ah[4], al[4];
                uint32_t off = 2u * ((a_row + mi * 16) * TSTR + ks * 16 + a_koff);
                LDSM4(ah[0], ah[1], ah[2], ah[3], sA_h + off);
                LDSM4(al[0], al[1], al[2], al[3], sA_l + off);
                #pragma unroll
                for (int ni = 0; ni < 4; ++ni) {
                    MMA(acc[mi][ni], ah, bh[ni]);
                    MMA(acc[mi][ni], ah, bl[ni]);
                    MMA(acc[mi][ni], al, bh[ni]);
                }
            }
        }
        __syncthreads();
    }
    float* Cm = g_D[i];
    #pragma unroll
    for (int mi = 0; mi < 4; ++mi)
        #pragma unroll
        for (int ni = 0; ni < 4; ++ni) {
            int row = bm + wm * 64 + mi * 16 + g;
            int col = bn + wn * 32 + ni * 8 + 2 * t;
            *(float2*)(Cm + (size_t)row * 4096 + col)       = make_float2(acc[mi][ni][0], acc[mi][ni][1]);
            *(float2*)(Cm + (size_t)(row + 8) * 4096 + col) = make_float2(acc[mi][ni][2], acc[mi][ni][3]);
        }
}

// ---- K9: gemm_out: single-pass A(fp16) x B(fp16), 3-stage, 3 CTAs/SM -------
#define OSTAGE (2 * TILEB)   // halves per stage (A, B)
__global__ __launch_bounds__(256, 3) void k_gemm_out(float* __restrict__ outp) {
    constexpr int KIT = 133;
    extern __shared__ __half smg[];   // 3 stages * OSTAGE
    int i = blockIdx.z, tid = threadIdx.x;
    int wid = tid >> 5, lane = tid & 31;
    int wm = wid & 1, wn = wid >> 1;
    int g = lane >> 2, t = lane & 3;
    int bm = blockIdx.y << 7, bn = blockIdx.x << 7;
    const __half* A  = g_Ath[i];
    const __half* Bh = g_Bth[i];
    float acc[4][4][4] = {};

    int a_row  = wm * 64 + (lane & 15);
    int a_koff = (lane >> 4) << 3;
    int b_row  = wn * 32 + (lane & 7) + ((lane >> 4) << 3);
    int b_koff = ((lane >> 3) & 1) << 3;

    #pragma unroll
    for (int s = 0; s < 2; ++s) {
        __half* b0 = smg + s * OSTAGE;
        int k0 = s << 5;
        cp_tile(A,  MQP, bm, k0, b0, tid);
        cp_tile(Bh, MQP, bn, k0, b0 + TILEB, tid);
        asm volatile("cp.async.commit_group;" ::: "memory");
    }
    for (int it = 0; it < KIT; ++it) {
        if (it + 1 < KIT) asm volatile("cp.async.wait_group 1;" ::: "memory");
        else              asm volatile("cp.async.wait_group 0;" ::: "memory");
        __syncthreads();
        int st = it % 3;
        uint32_t sA   = smem_u32(smg + st * OSTAGE);
        uint32_t sB_h = sA + 2 * TILEB;
        #pragma unroll
        for (int ks = 0; ks < 2; ++ks) {
            uint32_t bh[4][2];
            #pragma unroll
            for (int pr = 0; pr < 2; ++pr) {
                uint32_t off = 2u * ((b_row + pr * 16) * TSTR + ks * 16 + b_koff);
                LDSM4(bh[2*pr][0], bh[2*pr][1], bh[2*pr+1][0], bh[2*pr+1][1], sB_h + off);
            }
            #pragma unroll
            for (int mi = 0; mi < 4; ++mi) {
                uint32_t ah[4];
                uint32_t off = 2u * ((a_row + mi * 16) * TSTR + ks * 16 + a_koff);
                LDSM4(ah[0], ah[1], ah[2], ah[3], sA + off);
                #pragma unroll
                for (int ni = 0; ni < 4; ++ni)
                    MMA(acc[mi][ni], ah, bh[ni]);
            }
        }
        if (it + 2 < KIT) {
            __half* b0 = smg + ((it + 2) % 3) * OSTAGE;
            int k0 = (it + 2) << 5;
            cp_tile(A,  MQP, bm, k0, b0, tid);
            cp_tile(Bh, MQP, bn, k0, b0 + TILEB, tid);
            asm volatile("cp.async.commit_group;" ::: "memory");
        }
    }
    // fused parity-scatter epilogue
    #pragma unroll
    for (int mi = 0; mi < 4; ++mi)
        #pragma unroll
        for (int ni = 0; ni < 4; ++ni) {
            int row0 = bm + wm * 64 + mi * 16 + g;
            int col = bn + wn * 32 + ni * 8 + 2 * t;
            int par = col / IC, c = col - par * IC;
            int rx = par >> 1, ry = par & 1;
            #pragma unroll
            for (int h2 = 0; h2 < 2; ++h2) {
                int row = row0 + 8 * h2;
                if (row < MQ) {
                    int y0 = row / 65, x0 = row - y0 * 65;
                    int X = 2 * x0 + rx - 1, Y = 2 * y0 + ry - 1;
                    if ((unsigned)X < 128u && (unsigned)Y < 128u) {
                        float2 v = make_float2(0.25f * acc[mi][ni][2 * h2],
                                               0.25f * acc[mi][ni][2 * h2 + 1]);
                        *(float2*)(outp + (((size_t)i * IH + X) * IW + Y) * IC + c) = v;
                    }
                }
            }
        }
}

// ---- K3: fused score + fuse1, 2 rows/block, cp.async double-buffered bands -
// Bands: 6 rows x 4096, two buffers (196608 B). Every element actually read is
// a valid D location (masks imply in-range), so no zero-fill needed.
__global__ __launch_bounds__(512) void k_scoref() {
    extern __shared__ float sb[];   // [2][6][4096]
    int i = blockIdx.z;
    int p0 = blockIdx.x << 1;       // 2 output rows
    int tid = threadIdx.x;
    const float* D = g_D[i];
    float acc_s[4][8] = {};

    // prefetch band a into buf
    auto prefetch = [&](int a, float* buf) {
        int rbase = p0 - 2 + a * 64;
        #pragma unroll
        for (int j = 0; j < 12; ++j) {
            int idx = j * 512 + tid;        // 0..6143 (6 rows x 1024 float4)
            int s = idx >> 10, c4 = idx & 1023;
            int row = rbase + s;
            if ((unsigned)row < 4096u) {
                uint32_t d = smem_u32(buf + s * 4096 + c4 * 4);
                const void* src = D + (size_t)row * 4096 + c4 * 4;
                asm volatile("cp.async.ca.shared.global [%0], [%1], 16;" :: "r"(d), "l"(src));
            }
        }
        asm volatile("cp.async.commit_group;" ::: "memory");
    };

    prefetch(-1, sb);
    #pragma unroll
    for (int ai = 0; ai < 3; ++ai) {
        int a = ai - 1;
        float* cur = sb + (ai & 1) * 6 * 4096;
        if (ai < 2) {
            prefetch(ai, sb + ((ai + 1) & 1) * 6 * 4096);
            asm volatile("cp.async.wait_group 1;" ::: "memory");
        } else {
            asm volatile("cp.async.wait_group 0;" ::: "memory");
        }
        __syncthreads();
        #pragma unroll
        for (int r = 0; r < 4; ++r) {
            int pr = p0 - 1 + r;
            if ((unsigned)pr >= 4096u) continue;
            int xr = pr >> 6, yr = pr & 63;
            if ((unsigned)(xr + a) >= 64u) continue;
            #pragma unroll
            for (int k = 0; k < 8; ++k) {
                int l = tid + (k << 9);
                int u = l >> 6, v = l & 63;
                if ((unsigned)(u + a) >= 64u) continue;
                #pragma unroll
                for (int b = -1; b <= 1; ++b) {
                    if ((unsigned)(v + b) < 64u && (unsigned)(yr + b) < 64u)
                        acc_s[r][k] += cur[(r + b + 1) * 4096 + (l + a * 64 + b)];
                }
            }
        }
        __syncthreads();
    }
    // normalize S into sb rows 0..3 (buf0 region; all compute done)
    const float* nm = g_norm[i];
    #pragma unroll
    for (int k = 0; k < 8; ++k) {
        int l = tid + (k << 9);
        float inv = 1.0f / nm[l];
        #pragma unroll
        for (int r = 0; r < 4; ++r)
            sb[r * 4096 + l] = acc_s[r][k] * inv;
    }
    __syncthreads();
    float* F1 = g_S[i] + (size_t)p0 * 4096;
    #pragma unroll
    for (int k = 0; k < 8; ++k) {
        int q = tid + (k << 9);
        #pragma unroll
        for (int qi = 0; qi < 2; ++qi) {
            float s = 0.f;
            #pragma unroll
            for (int d = -1; d <= 1; ++d) {
                int qq = q + d;
                if ((unsigned)qq < 4096u)
                    s += sb[(qi + 1 + d) * 4096 + qq];
            }
            F1[(size_t)qi * 4096 + q] = s;
        }
    }
}

// -- K5: fused fuse2 + softmax, 2 rows/block; reads F1 (g_S), writes AT2 fp16
__global__ __launch_bounds__(256) void k_fuse2sm() {
    extern __shared__ float smf[];     // 4 * 4160 floats
    __shared__ float red[256];
    int i = blockIdx.z, pt0 = blockIdx.x << 1, tid = threadIdx.x;
    const float* F1 = g_S[i];

    #pragma unroll
    for (int d = 0; d < 4; ++d) {
        int pz = pt0 + d - 1;
        float* dst = smf + d * 4160;
        if ((unsigned)pz < 4096u) {
            int rd = ((pz & 63) << 6) | (pz >> 6);
            const float* row = F1 + (size_t)rd * 4096;
            #pragma unroll
            for (int j = 0; j < 16; ++j) {
                int c = tid + j * 256;
                dst[(c & 63) * 65 + (c >> 6)] = row[c];
            }
        } else {
            #pragma unroll
            for (int j = 0; j < 16; ++j) {
                int c = tid + j * 256;
                dst[(c & 63) * 65 + (c >> 6)] = 0.f;
            }
        }
    }
    __syncthreads();

    #pragma unroll
    for (int qi = 0; qi < 2; ++qi) {
        float vals[16], msk[16];
        float mx = -3.4e38f;
        #pragma unroll
        for (int j = 0; j < 16; ++j) {
            int qt = tid + j * 256;
            float s = 0.f;
            #pragma unroll
            for (int d = 0; d < 3; ++d) {
                int z = qt + d - 1;
                if ((unsigned)z < 4096u)
                    s += smf[(qi + d) * 4160 + (z >> 6) * 65 + (z & 63)];
            }
            float m = g_mmT[qt];
            msk[j] = m;
            float v = s * m * 10.0f;
            vals[j] = v;
            mx = fmaxf(mx, v);
        }
        red[tid] = mx; __syncthreads();
        #pragma unroll
        for (int s = 128; s > 0; s >>= 1) { if (tid < s) red[tid] = fmaxf(red[tid], red[tid + s]); __syncthreads(); }
        mx = red[0]; __syncthreads();
        float sum = 0.f;
        #pragma unroll
        for (int j = 0; j < 16; ++j) { vals[j] = expf(vals[j] - mx); sum += vals[j]; }
        red[tid] = sum; __syncthreads();
        #pragma unroll
        for (int s = 128; s > 0; s >>= 1) { if (tid < s) red[tid] += red[tid + s]; __syncthreads(); }
        float inv = 1.0f / red[0];
        __half* out = g_AT2[i] + (size_t)(pt0 + qi) * 4096;
        #pragma unroll
        for (int j = 0; j < 16; ++j) {
            int qt = tid + j * 256;
            out[qt] = __float2half_rn(vals[j] * inv * msk[j]);
        }
        __syncthreads();
    }
}

// ------ K7: build A-tilde (primed ordering, reads AT2 fp16, fp16 out) -------
__global__ void k_Abuild() {
    int i = blockIdx.z;
    int q0p = blockIdx.y;
    int lpp = blockIdx.x * 256 + threadIdx.x;
    int y0 = q0p / 65, x0 = q0p % 65;
    int vp = lpp / 65, up = lpp % 65;
    const __half* AT = g_AT2[i];
    float s = 0.f;
    #pragma unroll
    for (int a = 0; a < 2; ++a) {
        int xr = x0 - a, ur = up - a;
        if ((unsigned)xr < 64u && (unsigned)ur < 64u) {
            #pragma unroll
            for (int bo = 0; bo < 2; ++bo) {
                int yr = y0 - bo, vr = vp - bo;
                if ((unsigned)yr < 64u && (unsigned)vr < 64u)
                    s += __half2float(AT[(size_t)(yr * 64 + xr) * 4096 + (vr * 64 + ur)]);
            }
        }
    }
    g_Ath[i][(size_t)q0p * MQP + lpp] = __float2half_rn(s);
}

// ------ K8: build Bt[n][lp'] (fp16, primed K ordering) ----------------------
__global__ void k_Btbuild(const float* __restrict__ b) {
    int i = blockIdx.z;
    int n = blockIdx.y;
    int lpp = blockIdx.x * 256 + threadIdx.x;
    int par = n / IC, c = n - par * IC;
    int rx = par >> 1, ry = par & 1;
    int vp = lpp / 65, up = lpp % 65;
    int X = 2 * up + rx - 1, Y = 2 * vp + ry - 1;
    float val = 0.f;
    if (lpp < MQ && (unsigned)X < 128u && (unsigned)Y < 128u)
        val = b[(((size_t)i * IH + X) * IW + Y) * IC + c];
    g_Bth[i][(size_t)n * MQP + lpp] = __float2half_rn(val);
}

// ---------------- launch -----------------------------------------------------
extern "C" void kernel_launch(void* const* d_in, const int* in_sizes, int n_in,
                              void* d_out, int out_size) {
    const float* f    = (const float*)d_in[0];
    const float* b    = (const float*)d_in[1];
    const float* mask = (const float*)d_in[2];
    float* out = (float*)d_out;

    const int gemmD_smem = 8 * TILEB * 2;       // 81920 B
    const int gemmO_smem = 2 * OSTAGE * 3;      // 61440 B
    const int sf_smem    = 2 * 6 * 4096 * 4;    // 196608 B
    const int f2_smem    = 4 * 4160 * 4;        // 66560 B
    cudaFuncSetAttribute(k_gemm_D,   cudaFuncAttributeMaxDynamicSharedMemorySize, gemmD_smem);
    cudaFuncSetAttribute(k_gemm_out, cudaFuncAttributeMaxDynamicSharedMemorySize, gemmO_smem);
    cudaFuncSetAttribute(k_scoref,   cudaFuncAttributeMaxDynamicSharedMemorySize, sf_smem);
    cudaFuncSetAttribute(k_fuse2sm,  cudaFuncAttributeMaxDynamicSharedMemorySize, f2_smem);

    k_pack    <<<dim3(4096, 1, NB), 192>>>(f, b);
    k_norm_mm <<<dim3(32,   1, NB), 128>>>(mask);
    k_gemm_D  <<<dim3(32, 32, NB), 256, gemmD_smem>>>();
    k_scoref  <<<dim3(2048, 1, NB), 512, sf_smem>>>();
    k_fuse2sm <<<dim3(2048, 1, NB), 256, f2_smem>>>();
    k_Abuild  <<<dim3(17, MQ, NB), 256>>>();
    k_Btbuild <<<dim3(17, NOUT, NB), 256>>>(b);
    k_gemm_out<<<dim3(6, 34, NB), 256, gemmO_smem>>>(out);
}

// round 16
// speedup vs baseline: 1.2594x; 1.2224x over previous
#include <cuda_runtime.h>
#include <cuda_fp16.h>
#include <math.h>
#include <stdint.h>

#define NB   2
#define IH   128
#define IW   128
#define IC   192
#define LTOT 4096
#define MQ   4225   // 65*65
#define MQP  4352   // 34*128
#define NOUT 768
#define KD   192

// ---------------- scratch ----------------
__device__ __half g_fdh[NB][LTOT][KD], g_fdl[NB][LTOT][KD];
__device__ __half g_bdh[NB][LTOT][KD], g_bdl[NB][LTOT][KD];
__device__ float g_n2[NB][LTOT];
__device__ float g_norm[NB][LTOT];
__device__ float g_mmT[LTOT];                       // mask, transposed index
__device__ float g_D[NB][(size_t)LTOT * LTOT];      // D
__device__ float g_S[NB][(size_t)LTOT * LTOT];      // F1
__device__ __half g_AT2[NB][(size_t)LTOT * LTOT];   // attention (transposed), fp16
__device__ __half g_Ath[NB][(size_t)MQP * MQP];     // A-tilde (fp16)
__device__ __half g_Bth[NB][(size_t)NOUT * MQP];    // B (fp16)

__device__ __forceinline__ void split_h(float v, __half& h, __half& l) {
    h = __float2half_rn(v);
    l = __float2half_rn(v - __half2float(h));
}
__device__ __forceinline__ uint32_t smem_u32(const void* p) {
    uint32_t a;
    asm("{ .reg .u64 t; cvta.to.shared.u64 t, %1; cvt.u32.u64 %0, t; }" : "=r"(a) : "l"(p));
    return a;
}

#define MMA(ac, a, bb) \
    asm volatile("mma.sync.aligned.m16n8k16.row.col.f32.f16.f16.f32 " \
        "{%0,%1,%2,%3}, {%4,%5,%6,%7}, {%8,%9}, {%0,%1,%2,%3};" \
        : "+f"((ac)[0]), "+f"((ac)[1]), "+f"((ac)[2]), "+f"((ac)[3]) \
        : "r"((a)[0]), "r"((a)[1]), "r"((a)[2]), "r"((a)[3]), \
          "r"((bb)[0]), "r"((bb)[1]))

#define LDSM4(r0, r1, r2, r3, addr) \
    asm volatile("ldmatrix.sync.aligned.m8n8.x4.shared.b16 {%0,%1,%2,%3}, [%4];" \
        : "=r"(r0), "=r"(r1), "=r"(r2), "=r"(r3) : "r"(addr))

// ---------------- K1: downsample + pack fp16 hi/lo + |bd|^2 ---------------
__global__ void k_pack(const float* __restrict__ f, const float* __restrict__ b) {
    int i = blockIdx.z, p = blockIdx.x;
    int x = p >> 6, y = p & 63;
    size_t base = (((size_t)i * IH + 2 * x) * IW + 2 * y) * IC;
    int c = threadIdx.x;
    float fv = f[base + c], bv = b[base + c];
    __half h, l;
    split_h(fv, h, l); g_fdh[i][p][c] = h; g_fdl[i][p][c] = l;
    split_h(bv, h, l); g_bdh[i][p][c] = h; g_bdl[i][p][c] = l;

    __shared__ float sh[192];
    sh[c] = bv * bv;
    __syncthreads();
    if (c < 64) sh[c] += sh[c + 64] + sh[c + 128];
    __syncthreads();
    if (c < 32) {
        float v = sh[c] + sh[c + 32];
        #pragma unroll
        for (int o = 16; o > 0; o >>= 1) v += __shfl_down_sync(0xffffffffu, v, o);
        if (c == 0) g_n2[i][p] = v;
    }
}

// ---------------- K1b: patch norms + transposed mask ------------------------
__global__ void k_norm_mm(const float* __restrict__ mask) {
    int i = blockIdx.z;
    int l = blockIdx.x * 128 + threadIdx.x;
    int u = l >> 6, v = l & 63;
    float s = 0.f;
    #pragma unroll
    for (int a = -1; a <= 1; ++a)
        #pragma unroll
        for (int bo = -1; bo <= 1; ++bo) {
            int uu = u + a, vv = v + bo;
            if ((unsigned)uu < 64u && (unsigned)vv < 64u) s += g_n2[i][uu * 64 + vv];
        }
    g_norm[i][l] = fmaxf(sqrtf(s), 1e-4f);
    if (i == 0) {
        float ms = 0.f;
        #pragma unroll
        for (int a = -1; a <= 1; ++a)
            #pragma unroll
            for (int bo = -1; bo <= 1; ++bo) {
                int uu = u + a, vv = v + bo;
                if ((unsigned)uu < 64u && (unsigned)vv < 64u) ms += mask[(2 * uu) * IW + 2 * vv];
            }
        g_mmT[((l & 63) << 6) | (l >> 6)] = (ms == 0.0f) ? 1.0f : 0.0f;
    }
}

// ---- shared-tile copy helper ------------------------------------------------
#define TSTR 40
#define TILEB (128 * TSTR)

__device__ __forceinline__ void cp_tile(const __half* __restrict__ src,
                                        int ld, int row0, int k0,
                                        __half* dst, int tid) {
    #pragma unroll
    for (int j = 0; j < 2; ++j) {
        int idx = j * 256 + tid;
        int r = idx >> 2, cc = idx & 3;
        uint32_t d = smem_u32(dst + r * TSTR + cc * 8);
        const void* s = src + (size_t)(row0 + r) * ld + k0 + cc * 8;
        asm volatile("cp.async.ca.shared.global [%0], [%1], 16;" :: "r"(d), "l"(s));
    }
}

// ---- K2: gemm_D: D = fd*bd^T, fp16 3-pass, 2-stage, 2 CTAs/SM --------------
__global__ __launch_bounds__(256, 2) void k_gemm_D() {
    constexpr int KIT = 6;
    extern __shared__ __half smg[];
    int i = blockIdx.z, tid = threadIdx.x;
    int wid = tid >> 5, lane = tid & 31;
    int wm = wid & 1, wn = wid >> 1;
    int g = lane >> 2, t = lane & 3;
    int bm = blockIdx.y << 7, bn = blockIdx.x << 7;
    const __half* Ah = &g_fdh[i][0][0];
    const __half* Al = &g_fdl[i][0][0];
    const __half* Bh = &g_bdh[i][0][0];
    const __half* Bl = &g_bdl[i][0][0];
    float acc[4][4][4] = {};

    int a_row  = wm * 64 + (lane & 15);
    int a_koff = (lane >> 4) << 3;
    int b_row  = wn * 32 + (lane & 7) + ((lane >> 4) << 3);
    int b_koff = ((lane >> 3) & 1) << 3;

    {
        cp_tile(Ah, KD, bm, 0, smg, tid);
        cp_tile(Al, KD, bm, 0, smg + TILEB, tid);
        cp_tile(Bh, KD, bn, 0, smg + 2 * TILEB, tid);
        cp_tile(Bl, KD, bn, 0, smg + 3 * TILEB, tid);
        asm volatile("cp.async.commit_group;" ::: "memory");
    }
    for (int it = 0; it < KIT; ++it) {
        int st = it & 1;
        if (it + 1 < KIT) {
            __half* b0 = smg + (st ^ 1) * 4 * TILEB;
            int k0 = (it + 1) << 5;
            cp_tile(Ah, KD, bm, k0, b0, tid);
            cp_tile(Al, KD, bm, k0, b0 + TILEB, tid);
            cp_tile(Bh, KD, bn, k0, b0 + 2 * TILEB, tid);
            cp_tile(Bl, KD, bn, k0, b0 + 3 * TILEB, tid);
            asm volatile("cp.async.commit_group;" ::: "memory");
            asm volatile("cp.async.wait_group 1;" ::: "memory");
        } else {
            asm volatile("cp.async.wait_group 0;" ::: "memory");
        }
        __syncthreads();
        uint32_t sA_h = smem_u32(smg + st * 4 * TILEB);
        uint32_t sA_l = sA_h + TILEB * 2;
        uint32_t sB_h = sA_h + 4 * TILEB;
        uint32_t sB_l = sA_h + 6 * TILEB;
        #pragma unroll
        for (int ks = 0; ks < 2; ++ks) {
            uint32_t bh[4][2], bl[4][2];
            #pragma unroll
            for (int pr = 0; pr < 2; ++pr) {
                uint32_t off = 2u * ((b_row + pr * 16) * TSTR + ks * 16 + b_koff);
                LDSM4(bh[2*pr][0], bh[2*pr][1], bh[2*pr+1][0], bh[2*pr+1][1], sB_h + off);
                LDSM4(bl[2*pr][0], bl[2*pr][1], bl[2*pr+1][0], bl[2*pr+1][1], sB_l + off);
            }
            #pragma unroll
            for (int mi = 0; mi < 4; ++mi) {
                uint32_t ah[4], al[4];
                uint32_t off = 2u * ((a_row + mi * 16) * TSTR + ks * 16 + a_koff);
                LDSM4(ah[0], ah[1], ah[2], ah[3], sA_h + off);
                LDSM4(al[0], al[1], al[2], al[3], sA_l + off);
                #pragma unroll
                for (int ni = 0; ni < 4; ++ni) {
                    MMA(acc[mi][ni], ah, bh[ni]);
                    MMA(acc[mi][ni], ah, bl[ni]);
                    MMA(acc[mi][ni], al, bh[ni]);
                }
            }
        }
        __syncthreads();
    }
    float* Cm = g_D[i];
    #pragma unroll
    for (int mi = 0; mi < 4; ++mi)
        #pragma unroll
        for (int ni = 0; ni < 4; ++ni) {
            int row = bm + wm * 64 + mi * 16 + g;
            int col = bn + wn * 32 + ni * 8 + 2 * t;
            *(float2*)(Cm + (size_t)row * 4096 + col)       = make_float2(acc[mi][ni][0], acc[mi][ni][1]);
            *(float2*)(Cm + (size_t)(row + 8) * 4096 + col) = make_float2(acc[mi][ni][2], acc[mi][ni][3]);
        }
}

// ---- K9: gemm_out: single-pass A(fp16) x B(fp16), 3-stage, 3 CTAs/SM -------
#define OSTAGE (2 * TILEB)   // halves per stage (A, B)
__global__ __launch_bounds__(256, 3) void k_gemm_out(float* __restrict__ outp) {
    constexpr int KIT = 133;
    extern __shared__ __half smg[];   // 3 stages * OSTAGE
    int i = blockIdx.z, tid = threadIdx.x;
    int wid = tid >> 5, lane = tid & 31;
    int wm = wid & 1, wn = wid >> 1;
    int g = lane >> 2, t = lane & 3;
    int bm = blockIdx.y << 7, bn = blockIdx.x << 7;
    const __half* A  = g_Ath[i];
    const __half* Bh = g_Bth[i];
    float acc[4][4][4] = {};

    int a_row  = wm * 64 + (lane & 15);
    int a_koff = (lane >> 4) << 3;
    int b_row  = wn * 32 + (lane & 7) + ((lane >> 4) << 3);
    int b_koff = ((lane >> 3) & 1) << 3;

    #pragma unroll
    for (int s = 0; s < 2; ++s) {
        __half* b0 = smg + s * OSTAGE;
        int k0 = s << 5;
        cp_tile(A,  MQP, bm, k0, b0, tid);
        cp_tile(Bh, MQP, bn, k0, b0 + TILEB, tid);
        asm volatile("cp.async.commit_group;" ::: "memory");
    }
    for (int it = 0; it < KIT; ++it) {
        if (it + 1 < KIT) asm volatile("cp.async.wait_group 1;" ::: "memory");
        else              asm volatile("cp.async.wait_group 0;" ::: "memory");
        __syncthreads();
        int st = it % 3;
        uint32_t sA   = smem_u32(smg + st * OSTAGE);
        uint32_t sB_h = sA + 2 * TILEB;
        #pragma unroll
        for (int ks = 0; ks < 2; ++ks) {
            uint32_t bh[4][2];
            #pragma unroll
            for (int pr = 0; pr < 2; ++pr) {
                uint32_t off = 2u * ((b_row + pr * 16) * TSTR + ks * 16 + b_koff);
                LDSM4(bh[2*pr][0], bh[2*pr][1], bh[2*pr+1][0], bh[2*pr+1][1], sB_h + off);
            }
            #pragma unroll
            for (int mi = 0; mi < 4; ++mi) {
                uint32_t ah[4];
                uint32_t off = 2u * ((a_row + mi * 16) * TSTR + ks * 16 + a_koff);
                LDSM4(ah[0], ah[1], ah[2], ah[3], sA + off);
                #pragma unroll
                for (int ni = 0; ni < 4; ++ni)
                    MMA(acc[mi][ni], ah, bh[ni]);
            }
        }
        if (it + 2 < KIT) {
            __half* b0 = smg + ((it + 2) % 3) * OSTAGE;
            int k0 = (it + 2) << 5;
            cp_tile(A,  MQP, bm, k0, b0, tid);
            cp_tile(Bh, MQP, bn, k0, b0 + TILEB, tid);
            asm volatile("cp.async.commit_group;" ::: "memory");
        }
    }
    // fused parity-scatter epilogue
    #pragma unroll
    for (int mi = 0; mi < 4; ++mi)
        #pragma unroll
        for (int ni = 0; ni < 4; ++ni) {
            int row0 = bm + wm * 64 + mi * 16 + g;
            int col = bn + wn * 32 + ni * 8 + 2 * t;
            int par = col / IC, c = col - par * IC;
            int rx = par >> 1, ry = par & 1;
            #pragma unroll
            for (int h2 = 0; h2 < 2; ++h2) {
                int row = row0 + 8 * h2;
                if (row < MQ) {
                    int y0 = row / 65, x0 = row - y0 * 65;
                    int X = 2 * x0 + rx - 1, Y = 2 * y0 + ry - 1;
                    if ((unsigned)X < 128u && (unsigned)Y < 128u) {
                        float2 v = make_float2(0.25f * acc[mi][ni][2 * h2],
                                               0.25f * acc[mi][ni][2 * h2 + 1]);
                        *(float2*)(outp + (((size_t)i * IH + X) * IW + Y) * IC + c) = v;
                    }
                }
            }
        }
}

// ---- K3: fused score + fuse1, 8 output rows/block (round-13 structure) -----
__global__ __launch_bounds__(512) void k_scoref() {
    extern __shared__ float sb[];     // 12 * 4096 floats = 196608 B
    int i = blockIdx.z;
    int p0 = blockIdx.x << 3;         // 8 output rows
    int tid = threadIdx.x;
    const float* D = g_D[i];
    float acc_s[10][8] = {};

    #pragma unroll
    for (int a = -1; a <= 1; ++a) {
        __syncthreads();
        #pragma unroll
        for (int s = 0; s < 12; ++s) {
            int row = p0 - 2 + a * 64 + s;
            float4* dst = (float4*)(sb + s * 4096);
            if ((unsigned)row < 4096u) {
                const float4* src = (const float4*)(D + (size_t)row * 4096);
                dst[tid] = src[tid];
                dst[tid + 512] = src[tid + 512];
            } else {
                dst[tid] = make_float4(0.f, 0.f, 0.f, 0.f);
                dst[tid + 512] = make_float4(0.f, 0.f, 0.f, 0.f);
            }
        }
        __syncthreads();
        #pragma unroll
        for (int r = 0; r < 10; ++r) {
            int pr = p0 - 1 + r;
            if ((unsigned)pr >= 4096u) continue;
            int xr = pr >> 6, yr = pr & 63;
            if ((unsigned)(xr + a) >= 64u) continue;
            #pragma unroll
            for (int k = 0; k < 8; ++k) {
                int l = tid + (k << 9);
                int u = l >> 6, v = l & 63;
                if ((unsigned)(u + a) >= 64u) continue;
                #pragma unroll
                for (int b = -1; b <= 1; ++b) {
                    if ((unsigned)(v + b) < 64u && (unsigned)(yr + b) < 64u)
                        acc_s[r][k] += sb[(r + b + 1) * 4096 + (l + a * 64 + b)];
                }
            }
        }
    }
    __syncthreads();
    const float* nm = g_norm[i];
    #pragma unroll
    for (int k = 0; k < 8; ++k) {
        int l = tid + (k << 9);
        float inv = 1.0f / nm[l];
        #pragma unroll
        for (int r = 0; r < 10; ++r)
            sb[r * 4096 + l] = acc_s[r][k] * inv;
    }
    __syncthreads();
    float* F1 = g_S[i] + (size_t)p0 * 4096;
    #pragma unroll
    for (int k = 0; k < 8; ++k) {
        int q = tid + (k << 9);
        #pragma unroll
        for (int qi = 0; qi < 8; ++qi) {
            float s = 0.f;
            #pragma unroll
            for (int d = -1; d <= 1; ++d) {
                int qq = q + d;
                if ((unsigned)qq < 4096u)
                    s += sb[(qi + 1 + d) * 4096 + qq];
            }
            F1[(size_t)qi * 4096 + q] = s;
        }
    }
}

// -- K5: fused fuse2 + softmax (1 row/block); reads F1 (g_S), writes AT2 fp16
__global__ void k_fuse2sm() {
    extern __shared__ float smf[];     // 3 * 4160 floats
    __shared__ float red[256];
    int i = blockIdx.z, pt = blockIdx.x, tid = threadIdx.x;
    const float* F1 = g_S[i];

    #pragma unroll
    for (int d = 0; d < 3; ++d) {
        int pz = pt + d - 1;
        float* dst = smf + d * 4160;
        if ((unsigned)pz < 4096u) {
            int rd = ((pz & 63) << 6) | (pz >> 6);
            const float* row = F1 + (size_t)rd * 4096;
            #pragma unroll
            for (int j = 0; j < 16; ++j) {
                int c = tid + j * 256;
                dst[(c & 63) * 65 + (c >> 6)] = row[c];
            }
        } else {
            #pragma unroll
            for (int j = 0; j < 16; ++j) {
                int c = tid + j * 256;
                dst[(c & 63) * 65 + (c >> 6)] = 0.f;
            }
        }
    }
    __syncthreads();

    float vals[16], msk[16];
    float mx = -3.4e38f;
    #pragma unroll
    for (int j = 0; j < 16; ++j) {
        int qt = tid + j * 256;
        float s = 0.f;
        #pragma unroll
        for (int d = 0; d < 3; ++d) {
            int z = qt + d - 1;
            if ((unsigned)z < 4096u)
                s += smf[d * 4160 + (z >> 6) * 65 + (z & 63)];
        }
        float m = g_mmT[qt];
        msk[j] = m;
        float v = s * m * 10.0f;
        vals[j] = v;
        mx = fmaxf(mx, v);
    }
    red[tid] = mx; __syncthreads();
    #pragma unroll
    for (int s = 128; s > 0; s >>= 1) { if (tid < s) red[tid] = fmaxf(red[tid], red[tid + s]); __syncthreads(); }
    mx = red[0]; __syncthreads();
    float sum = 0.f;
    #pragma unroll
    for (int j = 0; j < 16; ++j) { vals[j] = expf(vals[j] - mx); sum += vals[j]; }
    red[tid] = sum; __syncthreads();
    #pragma unroll
    for (int s = 128; s > 0; s >>= 1) { if (tid < s) red[tid] += red[tid + s]; __syncthreads(); }
    float inv = 1.0f / red[0];
    __half* out = g_AT2[i] + (size_t)pt * 4096;
    #pragma unroll
    for (int j = 0; j < 16; ++j) {
        int qt = tid + j * 256;
        out[qt] = __float2half_rn(vals[j] * inv * msk[j]);
    }
}

// ------ K7: build A-tilde via smem row staging -------------------------------
__global__ __launch_bounds__(256) void k_Abuild() {
    __shared__ __half rows[4][4096];
    int i = blockIdx.z;
    int q0p = blockIdx.x;
    int y0 = q0p / 65, x0 = q0p % 65;
    int tid = threadIdx.x;
    const __half* AT = g_AT2[i];
    bool valid[4];
    #pragma unroll
    for (int a = 0; a < 2; ++a)
        #pragma unroll
        for (int bo = 0; bo < 2; ++bo) {
            int idx = a * 2 + bo;
            int xr = x0 - a, yr = y0 - bo;
            valid[idx] = ((unsigned)xr < 64u) && ((unsigned)yr < 64u);
            if (valid[idx]) {
                const uint4* src = (const uint4*)(AT + (size_t)(yr * 64 + xr) * 4096);
                uint4* dst = (uint4*)rows[idx];
                dst[tid] = src[tid];
                dst[tid + 256] = src[tid + 256];
            }
        }
    __syncthreads();
    __half* out = g_Ath[i] + (size_t)q0p * MQP;
    #pragma unroll
    for (int j = 0; j < 17; ++j) {
        int lpp = tid + j * 256;     // 0..4351
        int vp = lpp / 65, up = lpp - vp * 65;
        float s = 0.f;
        #pragma unroll
        for (int a = 0; a < 2; ++a) {
            int ur = up - a;
            if ((unsigned)ur >= 64u) continue;
            #pragma unroll
            for (int bo = 0; bo < 2; ++bo) {
                int vr = vp - bo;
                if (valid[a * 2 + bo] && (unsigned)vr < 64u)
                    s += __half2float(rows[a * 2 + bo][vr * 64 + ur]);
            }
        }
        out[lpp] = __float2half_rn(s);
    }
}

// ------ K8: build Bt[n][lp'] (fp16, primed K ordering) ----------------------
__global__ void k_Btbuild(const float* __restrict__ b) {
    int i = blockIdx.z;
    int n = blockIdx.y;
    int lpp = blockIdx.x * 256 + threadIdx.x;
    int par = n / IC, c = n - par * IC;
    int rx = par >> 1, ry = par & 1;
    int vp = lpp / 65, up = lpp % 65;
    int X = 2 * up + rx - 1, Y = 2 * vp + ry - 1;
    float val = 0.f;
    if (lpp < MQ && (unsigned)X < 128u && (unsigned)Y < 128u)
        val = b[(((size_t)i * IH + X) * IW + Y) * IC + c];
    g_Bth[i][(size_t)n * MQP + lpp] = __float2half_rn(val);
}

// ---------------- launch -----------------------------------------------------
extern "C" void kernel_launch(void* const* d_in, const int* in_sizes, int n_in,
                              void* d_out, int out_size) {
    const float* f    = (const float*)d_in[0];
    const float* b    = (const float*)d_in[1];
    const float* mask = (const float*)d_in[2];
    float* out = (float*)d_out;

    const int gemmD_smem = 8 * TILEB * 2;       // 81920 B
    const int gemmO_smem = 2 * OSTAGE * 3;      // 61440 B
    const int sf_smem    = 12 * 4096 * 4;       // 196608 B
    const int f2_smem    = 3 * 4160 * 4;        // 49920 B
    cudaFuncSetAttribute(k_gemm_D,   cudaFuncAttributeMaxDynamicSharedMemorySize, gemmD_smem);
    cudaFuncSetAttribute(k_gemm_out, cudaFuncAttributeMaxDynamicSharedMemorySize, gemmO_smem);
    cudaFuncSetAttribute(k_scoref,   cudaFuncAttributeMaxDynamicSharedMemorySize, sf_smem);
    cudaFuncSetAttribute(k_fuse2sm,  cudaFuncAttributeMaxDynamicSharedMemorySize, f2_smem);

    k_pack    <<<dim3(4096, 1, NB), 192>>>(f, b);
    k_norm_mm <<<dim3(32,   1, NB), 128>>>(mask);
    k_gemm_D  <<<dim3(32, 32, NB), 256, gemmD_smem>>>();
    k_scoref  <<<dim3(512, 1, NB), 512, sf_smem>>>();
    k_fuse2sm <<<dim3(4096, 1, NB), 256, f2_smem>>>();
    k_Abuild  <<<dim3(MQ, 1, NB), 256>>>();
    k_Btbuild <<<dim3(17, NOUT, NB), 256>>>(b);
    k_gemm_out<<<dim3(6, 34, NB), 256, gemmO_smem>>>(out);
}